// round 4
// baseline (speedup 1.0000x reference)
#include <cuda_runtime.h>
#include <cuda_bf16.h>
#include <cstdint>

// ---------------------------------------------------------------------------
// Problem constants
// ---------------------------------------------------------------------------
#define NC      100     // NUM_CLASSES
#define DDIM    512     // feature dim
#define SSPEC   10      // specialists
#define KCLUS   10      // cluster size
#define NPAD    112     // padded N (14 x n8 tiles)
#define NTILES  14
#define TILE_M  128
#define KC      64      // K per chunk
#define NCHUNK  (DDIM / KC)   // 8
#define THREADS 256

// Dynamic smem: 1KB align slack + 64KB fp32 staging (x2 buf) + 32KB bf16 A tiles
#define SMEM_DYN (1024 + 65536 + 32768)

// ---------------------------------------------------------------------------
// Device scratch (no allocations allowed -> __device__ globals)
// ---------------------------------------------------------------------------
__device__ __align__(16) float g_W1[DDIM * NC];     // folded (Wg + Wspec)  [512][100]
__device__ __align__(16) float g_W2[DDIM * NPAD];   // Weff = W1 @ Wc      [512][112]
__device__ __align__(16) float g_b1[NC];
__device__ __align__(16) float g_beff[NPAD];
__device__ int g_cls_s[NC];
__device__ int g_cls_k[NC];
// B fragments in native mma.sync m16n8k16 per-lane layout:
// [ks 0..31][nt 0..13][term hi/lo][lane 0..31] -> uint2 {b0, b1}
__device__ __align__(16) uint2 g_Bfrag[32 * NTILES * 2 * 32];

// ---------------------------------------------------------------------------
// Helpers
// ---------------------------------------------------------------------------
__device__ __forceinline__ uint32_t cvta_smem(const void* p) {
    return (uint32_t)__cvta_generic_to_shared(p);
}
__device__ __forceinline__ uint32_t sw128(uint32_t off) {
    return off ^ ((off >> 3) & 0x70);
}
__device__ __forceinline__ uint32_t pack_bf16(__nv_bfloat16 a, __nv_bfloat16 b) {
    return (uint32_t)__bfloat16_as_ushort(a) | ((uint32_t)__bfloat16_as_ushort(b) << 16);
}
__device__ __forceinline__ void cp_async16(uint32_t dst, const void* src) {
    asm volatile("cp.async.cg.shared.global [%0], [%1], 16;" :: "r"(dst), "l"(src));
}
__device__ __forceinline__ void ldmatrix_x4(uint32_t* r, uint32_t addr) {
    asm volatile("ldmatrix.sync.aligned.m8n8.x4.shared.b16 {%0,%1,%2,%3}, [%4];"
                 : "=r"(r[0]), "=r"(r[1]), "=r"(r[2]), "=r"(r[3]) : "r"(addr));
}
__device__ __forceinline__ void mma_bf16(float* d, const uint32_t* a, uint2 b) {
    asm volatile(
        "mma.sync.aligned.m16n8k16.row.col.f32.bf16.bf16.f32 "
        "{%0,%1,%2,%3}, {%4,%5,%6,%7}, {%8,%9}, {%0,%1,%2,%3};"
        : "+f"(d[0]), "+f"(d[1]), "+f"(d[2]), "+f"(d[3])
        : "r"(a[0]), "r"(a[1]), "r"(a[2]), "r"(a[3]), "r"(b.x), "r"(b.y));
}

// ---------------------------------------------------------------------------
// Precompute: fold whole network into Weff [512,112] + beff, then build
// mma-fragment images of bf16 hi/lo weight splits.
// ---------------------------------------------------------------------------
__global__ void prep0_kernel(const int* __restrict__ clusters,
                             const float* __restrict__ bg,
                             const float* __restrict__ bs) {
    int t = threadIdx.x;
    if (t < NC) {
        int s = t / KCLUS, k = t % KCLUS;
        int c = clusters[t];
        g_cls_s[c] = s;
        g_cls_k[c] = k;
    }
    __syncthreads();
    if (t < NC) {
        int s = g_cls_s[t], k = g_cls_k[t];
        float bsum = 0.f;
        #pragma unroll
        for (int sp = 0; sp < SSPEC; sp++) bsum += bs[sp * (KCLUS + 1) + KCLUS];
        g_b1[t] = bg[t] + bs[s * (KCLUS + 1) + k] +
                  (bsum - bs[s * (KCLUS + 1) + KCLUS]) * (1.0f / (NC - KCLUS));
    }
}

__global__ void prep1_kernel(const float* __restrict__ Wg,
                             const float* __restrict__ Ws) {
    int d = blockIdx.x;
    int c = threadIdx.x;
    if (c >= NC) return;
    int s = g_cls_s[c], k = g_cls_k[c];
    float dsum = 0.f;
    #pragma unroll
    for (int sp = 0; sp < SSPEC; sp++)
        dsum += Ws[sp * DDIM * (KCLUS + 1) + d * (KCLUS + 1) + KCLUS];
    float w = Wg[d * NC + c] + Ws[s * DDIM * (KCLUS + 1) + d * (KCLUS + 1) + k] +
              (dsum - Ws[s * DDIM * (KCLUS + 1) + d * (KCLUS + 1) + KCLUS]) *
                  (1.0f / (NC - KCLUS));
    g_W1[d * NC + c] = w;
}

__global__ void prep2_kernel(const float* __restrict__ Wc) {
    int d = blockIdx.x;   // 0..511
    int n = threadIdx.x;  // 0..111
    float acc = 0.f;
    if (n < NC) {
        #pragma unroll 4
        for (int k = 0; k < NC; k++) acc += g_W1[d * NC + k] * Wc[k * NC + n];
    }
    g_W2[d * NPAD + n] = acc;   // zero pad for n >= 100
}

__global__ void prep3_kernel(const float* __restrict__ Wc, const float* __restrict__ bc) {
    int c = threadIdx.x;
    if (c < NC) {
        float acc = bc[c];
        #pragma unroll 4
        for (int k = 0; k < NC; k++) acc += g_b1[k] * Wc[k * NC + c];
        g_beff[c] = acc;
    } else if (c < NPAD) {
        g_beff[c] = 0.f;
    }
}

// Build B fragments: for (ks, nt), lane holds
//   b0 = {B[k0][n], B[k0+1][n]},  b1 = {B[k0+8][n], B[k0+9][n]}
// with k0 = ks*16 + (lane&3)*2, n = nt*8 + (lane>>2).
__global__ void prep_frag_kernel() {
    int ks = blockIdx.x / NTILES;
    int nt = blockIdx.x % NTILES;
    int lane = threadIdx.x;
    int n  = nt * 8 + (lane >> 2);
    int k0 = ks * 16 + (lane & 3) * 2;

    float w00 = g_W2[(k0    ) * NPAD + n];
    float w01 = g_W2[(k0 + 1) * NPAD + n];
    float w80 = g_W2[(k0 + 8) * NPAD + n];
    float w81 = g_W2[(k0 + 9) * NPAD + n];

    __nv_bfloat16 h00 = __float2bfloat16(w00);
    __nv_bfloat16 h01 = __float2bfloat16(w01);
    __nv_bfloat16 h80 = __float2bfloat16(w80);
    __nv_bfloat16 h81 = __float2bfloat16(w81);
    __nv_bfloat16 l00 = __float2bfloat16(w00 - __bfloat162float(h00));
    __nv_bfloat16 l01 = __float2bfloat16(w01 - __bfloat162float(h01));
    __nv_bfloat16 l80 = __float2bfloat16(w80 - __bfloat162float(h80));
    __nv_bfloat16 l81 = __float2bfloat16(w81 - __bfloat162float(h81));

    int base = (ks * NTILES + nt) * 2;
    g_Bfrag[(base + 0) * 32 + lane] = make_uint2(pack_bf16(h00, h01), pack_bf16(h80, h81));
    g_Bfrag[(base + 1) * 32 + lane] = make_uint2(pack_bf16(l00, l01), pack_bf16(l80, l81));
}

// ---------------------------------------------------------------------------
// Main GEMM: out = relu(x @ Weff + beff) via mma.sync bf16, 3-term split.
// 8 warps: warp grid 4(M) x 2(N); warp tile m32 x n56 (7 n8 tiles, padded).
// ---------------------------------------------------------------------------
__global__ __launch_bounds__(THREADS, 2)
void gemm_main_kernel(const float* __restrict__ x, float* __restrict__ out) {
    extern __shared__ unsigned char smem_raw[];
    uint32_t sb0 = cvta_smem(smem_raw);
    uint32_t sb = (sb0 + 1023u) & ~1023u;
    unsigned char* smem = smem_raw + (sb - sb0);

    const uint32_t XS = sb;                 // [2][128][64] f32 staging (64KB)
    const uint32_t AH = sb + 65536;         // [128][64] bf16 hi, sw128 (16KB)
    const uint32_t AL = AH + 16384;         // lo (16KB)
    float* xs = (float*)smem;

    const int tid  = threadIdx.x;
    const int wid  = tid >> 5;
    const int lane = tid & 31;
    const int wm   = wid >> 1;              // 0..3 -> m32 tile
    const int wn   = wid & 1;               // 0..1 -> n56 half

    const float* xt = x + (size_t)blockIdx.x * TILE_M * DDIM;

    float acc[2][7][4];
    #pragma unroll
    for (int mt = 0; mt < 2; mt++)
        #pragma unroll
        for (int j = 0; j < 7; j++)
            #pragma unroll
            for (int q = 0; q < 4; q++) acc[mt][j][q] = 0.f;

    // prefetch chunk 0 into staging buf 0
    #pragma unroll
    for (int i = 0; i < 8; i++) {
        int slot = tid + i * THREADS;       // 0..2047
        int r = slot >> 4, q = slot & 15;
        cp_async16(XS + (uint32_t)(r * 64 + q * 4) * 4,
                   xt + (size_t)r * DDIM + q * 4);
    }
    asm volatile("cp.async.commit_group;" ::: "memory");

    for (int ch = 0; ch < NCHUNK; ch++) {
        if (ch + 1 < NCHUNK) {
            uint32_t bufoff = (uint32_t)((ch + 1) & 1) * 32768;
            #pragma unroll
            for (int i = 0; i < 8; i++) {
                int slot = tid + i * THREADS;
                int r = slot >> 4, q = slot & 15;
                cp_async16(XS + bufoff + (uint32_t)(r * 64 + q * 4) * 4,
                           xt + (size_t)r * DDIM + (ch + 1) * KC + q * 4);
            }
            asm volatile("cp.async.commit_group;" ::: "memory");
            asm volatile("cp.async.wait_group 1;" ::: "memory");
        } else {
            asm volatile("cp.async.wait_group 0;" ::: "memory");
        }
        __syncthreads();

        // ---- convert staged fp32 -> bf16 hi/lo, swizzled STS ----
        const float* xb = xs + (ch & 1) * 8192;
        #pragma unroll
        for (int i = 0; i < 8; i++) {
            int slot = tid + i * THREADS;
            int r = slot >> 4, q = slot & 15;
            float4 v = *(const float4*)(xb + r * 64 + q * 4);
            __nv_bfloat16 h0 = __float2bfloat16(v.x);
            __nv_bfloat16 h1 = __float2bfloat16(v.y);
            __nv_bfloat16 h2 = __float2bfloat16(v.z);
            __nv_bfloat16 h3 = __float2bfloat16(v.w);
            __nv_bfloat16 l0 = __float2bfloat16(v.x - __bfloat162float(h0));
            __nv_bfloat16 l1 = __float2bfloat16(v.y - __bfloat162float(h1));
            __nv_bfloat16 l2 = __float2bfloat16(v.z - __bfloat162float(h2));
            __nv_bfloat16 l3 = __float2bfloat16(v.w - __bfloat162float(h3));
            uint32_t off = sw128((uint32_t)(r * 128 + q * 8));
            *(uint2*)(smem + 65536 + off)         = make_uint2(pack_bf16(h0, h1), pack_bf16(h2, h3));
            *(uint2*)(smem + 65536 + 16384 + off) = make_uint2(pack_bf16(l0, l1), pack_bf16(l2, l3));
        }
        __syncthreads();

        // ---- MMA over 4 k16 steps ----
        #pragma unroll
        for (int ks = 0; ks < 4; ks++) {
            const int gks = ch * 4 + ks;
            uint32_t a_h[2][4], a_l[2][4];
            #pragma unroll
            for (int mt = 0; mt < 2; mt++) {
                int row  = wm * 32 + mt * 16 + ((lane >> 3) & 1) * 8 + (lane & 7);
                int half = lane >> 4;
                uint32_t off = sw128((uint32_t)(row * 128 + ks * 32 + half * 16));
                ldmatrix_x4(a_h[mt], AH + off);
                ldmatrix_x4(a_l[mt], AL + off);
            }
            const uint2* bp = g_Bfrag + ((size_t)(gks * NTILES + wn * 7) * 2) * 32 + lane;
            #pragma unroll
            for (int j = 0; j < 7; j++) {
                uint2 bh = bp[(j * 2 + 0) * 32];
                uint2 bl = bp[(j * 2 + 1) * 32];
                #pragma unroll
                for (int mt = 0; mt < 2; mt++) {
                    mma_bf16(acc[mt][j], a_h[mt], bh);
                    mma_bf16(acc[mt][j], a_h[mt], bl);
                    mma_bf16(acc[mt][j], a_l[mt], bh);
                }
            }
        }
        __syncthreads();   // protect A tiles before next chunk's convert
    }

    // ---- epilogue: bias + relu + direct STG (no smem round trip) ----
    const int g  = lane >> 2;
    const int tq = lane & 3;
    const int mrow = blockIdx.x * TILE_M + wm * 32;
    #pragma unroll
    for (int mt = 0; mt < 2; mt++) {
        #pragma unroll
        for (int j = 0; j < 7; j++) {
            int c = wn * 56 + j * 8 + tq * 2;
            if (c < NC) {
                float2 bv = *(const float2*)&g_beff[c];
                int r0 = mrow + mt * 16 + g;
                float v0 = acc[mt][j][0] + bv.x;
                float v1 = acc[mt][j][1] + bv.y;
                float v2 = acc[mt][j][2] + bv.x;
                float v3 = acc[mt][j][3] + bv.y;
                float2 o0 = make_float2(v0 > 0.f ? v0 : 0.f, v1 > 0.f ? v1 : 0.f);
                float2 o1 = make_float2(v2 > 0.f ? v2 : 0.f, v3 > 0.f ? v3 : 0.f);
                *(float2*)(out + (size_t)r0 * NC + c)       = o0;
                *(float2*)(out + (size_t)(r0 + 8) * NC + c) = o1;
            }
        }
    }
}

// ---------------------------------------------------------------------------
// Launch
// ---------------------------------------------------------------------------
extern "C" void kernel_launch(void* const* d_in, const int* in_sizes, int n_in,
                              void* d_out, int out_size) {
    const float* x        = (const float*)d_in[0];
    const float* Wg       = (const float*)d_in[1];
    const float* bg       = (const float*)d_in[2];
    const float* Ws       = (const float*)d_in[3];
    const float* bs       = (const float*)d_in[4];
    const float* Wc       = (const float*)d_in[5];
    const float* bc       = (const float*)d_in[6];
    const int*   clusters = (const int*)d_in[7];
    float* out = (float*)d_out;

    int Btot = in_sizes[0] / DDIM;      // 131072
    int grid = Btot / TILE_M;           // 1024

    cudaFuncSetAttribute(gemm_main_kernel,
                         cudaFuncAttributeMaxDynamicSharedMemorySize, SMEM_DYN);

    prep0_kernel<<<1, 128>>>(clusters, bg, bs);
    prep1_kernel<<<DDIM, 128>>>(Wg, Ws);
    prep2_kernel<<<DDIM, NPAD>>>(Wc);
    prep3_kernel<<<1, 128>>>(Wc, bc);
    prep_frag_kernel<<<32 * NTILES, 32>>>();
    gemm_main_kernel<<<grid, THREADS, SMEM_DYN>>>(x, out);
}

// round 5
// speedup vs baseline: 1.2116x; 1.2116x over previous
#include <cuda_runtime.h>
#include <cuda_fp16.h>
#include <cstdint>

// ---------------------------------------------------------------------------
// Problem constants
// ---------------------------------------------------------------------------
#define NC      100     // NUM_CLASSES
#define DDIM    512     // feature dim
#define SSPEC   10      // specialists
#define KCLUS   10      // cluster size
#define NPAD    104     // padded N (13 x n8 tiles)
#define NTILES  13
#define TILE_M  128
#define KC      64      // K per chunk
#define NCHUNK  (DDIM / KC)   // 8
#define THREADS 256

// Dynamic smem: 1KB align slack + 64KB fp32 staging (x2 buf) + 16KB fp16 A tile
#define SMEM_DYN (1024 + 65536 + 16384)

// ---------------------------------------------------------------------------
// Device scratch (no allocations allowed -> __device__ globals)
// ---------------------------------------------------------------------------
__device__ __align__(16) float g_W1[DDIM * NC];     // folded (Wg + Wspec)  [512][100]
__device__ __align__(16) float g_b1[NC];
__device__ __align__(16) float g_beff[NPAD];
__device__ int g_cls_s[NC];
__device__ int g_cls_k[NC];
// B fragments in native mma.sync m16n8k16 per-lane layout:
// [ks 0..31][nt 0..12][plane hi/lo][lane 0..31] -> uint2 {b0, b1}
__device__ __align__(16) uint2 g_Bfrag[32 * NTILES * 2 * 32];

// ---------------------------------------------------------------------------
// Helpers
// ---------------------------------------------------------------------------
__device__ __forceinline__ uint32_t cvta_smem(const void* p) {
    return (uint32_t)__cvta_generic_to_shared(p);
}
__device__ __forceinline__ uint32_t sw128(uint32_t off) {
    return off ^ ((off >> 3) & 0x70);
}
__device__ __forceinline__ uint32_t pack_f16(__half a, __half b) {
    return (uint32_t)__half_as_ushort(a) | ((uint32_t)__half_as_ushort(b) << 16);
}
__device__ __forceinline__ void cp_async16(uint32_t dst, const void* src) {
    asm volatile("cp.async.cg.shared.global [%0], [%1], 16;" :: "r"(dst), "l"(src));
}
__device__ __forceinline__ void ldmatrix_x4(uint32_t* r, uint32_t addr) {
    asm volatile("ldmatrix.sync.aligned.m8n8.x4.shared.b16 {%0,%1,%2,%3}, [%4];"
                 : "=r"(r[0]), "=r"(r[1]), "=r"(r[2]), "=r"(r[3]) : "r"(addr));
}
__device__ __forceinline__ void mma_f16(float* d, const uint32_t* a, uint2 b) {
    asm volatile(
        "mma.sync.aligned.m16n8k16.row.col.f32.f16.f16.f32 "
        "{%0,%1,%2,%3}, {%4,%5,%6,%7}, {%8,%9}, {%0,%1,%2,%3};"
        : "+f"(d[0]), "+f"(d[1]), "+f"(d[2]), "+f"(d[3])
        : "r"(a[0]), "r"(a[1]), "r"(a[2]), "r"(a[3]), "r"(b.x), "r"(b.y));
}

// ---------------------------------------------------------------------------
// prepA: cluster map + folded first-layer bias g_b1
// ---------------------------------------------------------------------------
__global__ void prepA_kernel(const int* __restrict__ clusters,
                             const float* __restrict__ bg,
                             const float* __restrict__ bs) {
    int t = threadIdx.x;
    if (t < NC) {
        int s = t / KCLUS, k = t % KCLUS;
        int c = clusters[t];
        g_cls_s[c] = s;
        g_cls_k[c] = k;
    }
    __syncthreads();
    if (t < NC) {
        int s = g_cls_s[t], k = g_cls_k[t];
        float bsum = 0.f;
        #pragma unroll
        for (int sp = 0; sp < SSPEC; sp++) bsum += bs[sp * (KCLUS + 1) + KCLUS];
        g_b1[t] = bg[t] + bs[s * (KCLUS + 1) + k] +
                  (bsum - bs[s * (KCLUS + 1) + KCLUS]) * (1.0f / (NC - KCLUS));
    }
}

// ---------------------------------------------------------------------------
// prepB: fold Wg + specialist weights -> g_W1 [512][100]
// ---------------------------------------------------------------------------
__global__ void prepB_kernel(const float* __restrict__ Wg,
                             const float* __restrict__ Ws) {
    int d = blockIdx.x;
    int c = threadIdx.x;
    if (c >= NC) return;
    int s = g_cls_s[c], k = g_cls_k[c];
    float dsum = 0.f;
    #pragma unroll
    for (int sp = 0; sp < SSPEC; sp++)
        dsum += Ws[sp * DDIM * (KCLUS + 1) + d * (KCLUS + 1) + KCLUS];
    float w = Wg[d * NC + c] + Ws[s * DDIM * (KCLUS + 1) + d * (KCLUS + 1) + k] +
              (dsum - Ws[s * DDIM * (KCLUS + 1) + d * (KCLUS + 1) + KCLUS]) *
                  (1.0f / (NC - KCLUS));
    g_W1[d * NC + c] = w;
}

// ---------------------------------------------------------------------------
// prepC: Weff = W1 @ Wc computed directly into fp16 hi/lo mma fragments.
// One block per (ks, nt); lane owns (n = nt*8 + l/4, k0 = ks*16 + (l%4)*2)
// and computes Weff at (k0, n), (k0+1, n), (k0+8, n), (k0+9, n).
// ---------------------------------------------------------------------------
__global__ void prepC_kernel(const float* __restrict__ Wc) {
    int ks = blockIdx.x / NTILES;
    int nt = blockIdx.x % NTILES;
    int lane = threadIdx.x;
    int n  = nt * 8 + (lane >> 2);
    int k0 = ks * 16 + (lane & 3) * 2;

    float w0 = 0.f, w1 = 0.f, w2 = 0.f, w3 = 0.f;
    if (n < NC) {
        const float* r0 = g_W1 + (k0    ) * NC;
        const float* r1 = g_W1 + (k0 + 1) * NC;
        const float* r2 = g_W1 + (k0 + 8) * NC;
        const float* r3 = g_W1 + (k0 + 9) * NC;
        #pragma unroll 4
        for (int t = 0; t < NC; t++) {
            float wc = Wc[t * NC + n];
            w0 += r0[t] * wc;
            w1 += r1[t] * wc;
            w2 += r2[t] * wc;
            w3 += r3[t] * wc;
        }
    }
    __half h0 = __float2half_rn(w0), h1 = __float2half_rn(w1);
    __half h2 = __float2half_rn(w2), h3 = __float2half_rn(w3);
    __half l0 = __float2half_rn(w0 - __half2float(h0));
    __half l1 = __float2half_rn(w1 - __half2float(h1));
    __half l2 = __float2half_rn(w2 - __half2float(h2));
    __half l3 = __float2half_rn(w3 - __half2float(h3));

    int base = (ks * NTILES + nt) * 2;
    g_Bfrag[(base + 0) * 32 + lane] = make_uint2(pack_f16(h0, h1), pack_f16(h2, h3));
    g_Bfrag[(base + 1) * 32 + lane] = make_uint2(pack_f16(l0, l1), pack_f16(l2, l3));
}

// ---------------------------------------------------------------------------
// prepD: beff = b1 @ Wc + bc  (one block per output col, warp-parallel dot)
// ---------------------------------------------------------------------------
__global__ void prepD_kernel(const float* __restrict__ Wc,
                             const float* __restrict__ bc) {
    int c = blockIdx.x;
    int lane = threadIdx.x;
    float s = 0.f;
    if (c < NC) {
        #pragma unroll
        for (int k = lane; k < NC; k += 32)
            s += g_b1[k] * Wc[k * NC + c];
    }
    #pragma unroll
    for (int o = 16; o > 0; o >>= 1)
        s += __shfl_xor_sync(0xFFFFFFFFu, s, o);
    if (lane == 0)
        g_beff[c] = (c < NC) ? (s + bc[c]) : 0.f;
}

// ---------------------------------------------------------------------------
// Main GEMM: out = relu(x @ Weff + beff) via mma.sync fp16.
// x single fp16 plane; W split into fp16 hi + lo (2 MMAs per k16).
// 8 warps: warp grid 4(M) x 2(N); warp tile m32 x n56/n48.
// ---------------------------------------------------------------------------
__global__ __launch_bounds__(THREADS, 2)
void gemm_main_kernel(const float* __restrict__ x, float* __restrict__ out) {
    extern __shared__ unsigned char smem_raw[];
    uint32_t sb0 = cvta_smem(smem_raw);
    uint32_t sb = (sb0 + 1023u) & ~1023u;
    unsigned char* smem = smem_raw + (sb - sb0);

    const uint32_t XS = sb;                 // [2][128][64] f32 staging (64KB)
    const uint32_t AH = sb + 65536;         // [128][64] fp16 A tile, sw128 (16KB)
    float* xs = (float*)smem;

    const int tid  = threadIdx.x;
    const int wid  = tid >> 5;
    const int lane = tid & 31;
    const int wm   = wid >> 1;              // 0..3 -> m32 tile
    const int wn   = wid & 1;               // 0..1 -> n half (7 / 6 tiles)
    const int jmax = wn ? 6 : 7;

    const float* xt = x + (size_t)blockIdx.x * TILE_M * DDIM;

    float acc[2][7][4];
    #pragma unroll
    for (int mt = 0; mt < 2; mt++)
        #pragma unroll
        for (int j = 0; j < 7; j++)
            #pragma unroll
            for (int q = 0; q < 4; q++) acc[mt][j][q] = 0.f;

    // prefetch chunk 0 into staging buf 0
    #pragma unroll
    for (int i = 0; i < 8; i++) {
        int slot = tid + i * THREADS;       // 0..2047
        int r = slot >> 4, q = slot & 15;
        cp_async16(XS + (uint32_t)(r * 64 + q * 4) * 4,
                   xt + (size_t)r * DDIM + q * 4);
    }
    asm volatile("cp.async.commit_group;" ::: "memory");

    for (int ch = 0; ch < NCHUNK; ch++) {
        if (ch + 1 < NCHUNK) {
            uint32_t bufoff = (uint32_t)((ch + 1) & 1) * 32768;
            #pragma unroll
            for (int i = 0; i < 8; i++) {
                int slot = tid + i * THREADS;
                int r = slot >> 4, q = slot & 15;
                cp_async16(XS + bufoff + (uint32_t)(r * 64 + q * 4) * 4,
                           xt + (size_t)r * DDIM + (ch + 1) * KC + q * 4);
            }
            asm volatile("cp.async.commit_group;" ::: "memory");
            asm volatile("cp.async.wait_group 1;" ::: "memory");
        } else {
            asm volatile("cp.async.wait_group 0;" ::: "memory");
        }
        // staging slots are read by the same thread that issued them: no sync

        // ---- convert staged fp32 -> fp16, swizzled STS ----
        const float* xb = xs + (ch & 1) * 8192;
        #pragma unroll
        for (int i = 0; i < 8; i++) {
            int slot = tid + i * THREADS;
            int r = slot >> 4, q = slot & 15;
            float4 v = *(const float4*)(xb + r * 64 + q * 4);
            __half2 p01 = __floats2half2_rn(v.x, v.y);
            __half2 p23 = __floats2half2_rn(v.z, v.w);
            uint32_t off = sw128((uint32_t)(r * 128 + q * 8));
            *(uint2*)(smem + 65536 + off) =
                make_uint2(*(uint32_t*)&p01, *(uint32_t*)&p23);
        }
        __syncthreads();

        // ---- MMA over 4 k16 steps ----
        #pragma unroll
        for (int ks = 0; ks < 4; ks++) {
            const int gks = ch * 4 + ks;
            uint32_t a_h[2][4];
            #pragma unroll
            for (int mt = 0; mt < 2; mt++) {
                int row  = wm * 32 + mt * 16 + ((lane >> 3) & 1) * 8 + (lane & 7);
                int half = lane >> 4;
                uint32_t off = sw128((uint32_t)(row * 128 + ks * 32 + half * 16));
                ldmatrix_x4(a_h[mt], AH + off);
            }
            const uint2* bp = g_Bfrag + ((size_t)(gks * NTILES + wn * 7) * 2) * 32 + lane;
            #pragma unroll
            for (int j = 0; j < 7; j++) {
                if (j < jmax) {
                    uint2 bh = bp[(j * 2 + 0) * 32];
                    uint2 bl = bp[(j * 2 + 1) * 32];
                    #pragma unroll
                    for (int mt = 0; mt < 2; mt++) {
                        mma_f16(acc[mt][j], a_h[mt], bh);
                        mma_f16(acc[mt][j], a_h[mt], bl);
                    }
                }
            }
        }
        __syncthreads();   // protect A tile before next chunk's convert
    }

    // ---- epilogue: bias + relu + direct STG ----
    const int g  = lane >> 2;
    const int tq = lane & 3;
    const int mrow = blockIdx.x * TILE_M + wm * 32;
    #pragma unroll
    for (int mt = 0; mt < 2; mt++) {
        #pragma unroll
        for (int j = 0; j < 7; j++) {
            if (j < jmax) {
                int c = wn * 56 + j * 8 + tq * 2;
                if (c < NC) {
                    float2 bv = *(const float2*)&g_beff[c];
                    int r0 = mrow + mt * 16 + g;
                    float v0 = acc[mt][j][0] + bv.x;
                    float v1 = acc[mt][j][1] + bv.y;
                    float v2 = acc[mt][j][2] + bv.x;
                    float v3 = acc[mt][j][3] + bv.y;
                    float2 o0 = make_float2(v0 > 0.f ? v0 : 0.f, v1 > 0.f ? v1 : 0.f);
                    float2 o1 = make_float2(v2 > 0.f ? v2 : 0.f, v3 > 0.f ? v3 : 0.f);
                    *(float2*)(out + (size_t)r0 * NC + c)       = o0;
                    *(float2*)(out + (size_t)(r0 + 8) * NC + c) = o1;
                }
            }
        }
    }
}

// ---------------------------------------------------------------------------
// Launch
// ---------------------------------------------------------------------------
extern "C" void kernel_launch(void* const* d_in, const int* in_sizes, int n_in,
                              void* d_out, int out_size) {
    const float* x        = (const float*)d_in[0];
    const float* Wg       = (const float*)d_in[1];
    const float* bg       = (const float*)d_in[2];
    const float* Ws       = (const float*)d_in[3];
    const float* bs       = (const float*)d_in[4];
    const float* Wc       = (const float*)d_in[5];
    const float* bc       = (const float*)d_in[6];
    const int*   clusters = (const int*)d_in[7];
    float* out = (float*)d_out;

    int Btot = in_sizes[0] / DDIM;      // 131072
    int grid = Btot / TILE_M;           // 1024

    cudaFuncSetAttribute(gemm_main_kernel,
                         cudaFuncAttributeMaxDynamicSharedMemorySize, SMEM_DYN);

    prepA_kernel<<<1, 128>>>(clusters, bg, bs);
    prepB_kernel<<<DDIM, 128>>>(Wg, Ws);
    prepD_kernel<<<NPAD, 32>>>(Wc, bc);
    prepC_kernel<<<32 * NTILES, 32>>>(Wc);
    gemm_main_kernel<<<grid, THREADS, SMEM_DYN>>>(x, out);
}